// round 4
// baseline (speedup 1.0000x reference)
#include <cuda_runtime.h>
#include <math.h>

// Problem constants (fixed by the reference)
#define NATOMS     8192
#define MAX_PAIRS  (64 * 8192)     // 524288
#define CUT2       25.0f           // cutoff_upper^2; cutoff_lower = 0
#define NCELL1     9               // 45.0 / 5.0
#define NCELLS     (NCELL1 * NCELL1 * NCELL1)   // 729
#define CAP        48              // bucket capacity (Poisson mean 11.2)
#define MASK_WORDS 256             // 8192 bits per row
#define NBLK       256             // grid size (all-resident by construction)
#define NTHR       512             // 16 warps; each warp owns 2 rows
#define ROWS_PER_BLOCK 32
#define SLOTS_PER_BLOCK (MAX_PAIRS / NBLK)   // 2048
#define FULLMASK   0xffffffffu

// Scratch (no allocations allowed -> device globals; zero-initialized at load)
__device__ int      g_cell_cnt[NCELLS];
__device__ float4   g_bpos[NCELLS * CAP];    // (x, y, z, atom_idx bits)
__device__ int      g_bbatch[NCELLS * CAP];
__device__ unsigned g_state[NBLK];           // decoupled-lookback state
__device__ volatile unsigned g_bar_count;    // grid barrier
__device__ volatile unsigned g_bar_gen;

// d2 with the SAME rounding as the reference: rounded products, then ((a+b)+c).
__device__ __forceinline__ float d2_exact(float dx, float dy, float dz) {
    float a = __fmul_rn(dx, dx);
    float b = __fmul_rn(dy, dy);
    float c = __fmul_rn(dz, dz);
    return __fadd_rn(__fadd_rn(a, b), c);
}

__device__ __forceinline__ int cell_coord(float p) {
    int c = (int)(p * 0.2f);
    return c < 0 ? 0 : (c > NCELL1 - 1 ? NCELL1 - 1 : c);
}

// Grid-wide software barrier. SAFE because all NBLK blocks are co-resident:
// __launch_bounds__(512,2) caps regs at 64, smem 33KB -> 2 blocks/SM,
// 148 SMs * 2 = 296 >= 256.
__device__ __forceinline__ void gbar() {
    __threadfence();
    __syncthreads();
    if (threadIdx.x == 0) {
        const unsigned gen = g_bar_gen;
        if (atomicAdd((unsigned*)&g_bar_count, 1u) == NBLK - 1u) {
            g_bar_count = 0;
            __threadfence();
            g_bar_gen = gen + 1u;
        } else {
            while (g_bar_gen == gen) { __nanosleep(32); }
        }
    }
    __syncthreads();
    __threadfence();
}

// Build the hit bitmask for row i (warp-cooperative, order-independent).
__device__ __forceinline__ void build_row_mask(
    const int i, const float pix, const float piy, const float piz,
    const int bi, unsigned* __restrict__ mask, const int lane)
{
    const int cx = cell_coord(pix), cy = cell_coord(piy), cz = cell_coord(piz);
    const int x0 = max(cx - 1, 0), x1 = min(cx + 1, NCELL1 - 1);
    const int y0 = max(cy - 1, 0), y1 = min(cy + 1, NCELL1 - 1);
    const int z0 = max(cz - 1, 0), z1 = min(cz + 1, NCELL1 - 1);

    for (int ix = x0; ix <= x1; ix++) {
        for (int iy = y0; iy <= y1; iy++) {
            for (int iz = z0; iz <= z1; iz++) {
                const int c = ix * 81 + iy * 9 + iz;
                int cnt = g_cell_cnt[c];
                if (cnt > CAP) cnt = CAP;
                for (int s = lane; s < cnt; s += 32) {
                    const float4 pj = g_bpos[c * CAP + s];
                    const float dx = pix - pj.x;
                    const float dy = piy - pj.y;
                    const float dz = piz - pj.z;
                    const float d2 = d2_exact(dx, dy, dz);
                    const int j = __float_as_int(pj.w);
                    if (d2 < CUT2 && j != i && g_bbatch[c * CAP + s] == bi) {
                        atomicOr(&mask[j >> 5], 1u << (j & 31));
                    }
                }
            }
        }
    }
}

// ---------------------------------------------------------------------------
// ONE kernel, 4 phases:
//  0: zero cell counts / lookback state / shared masks      -> grid barrier
//  1: parallel bucketed cell-list build                     -> grid barrier
//  2: per-row masks -> counts -> decoupled lookback -> ordered writes
//  3: poll final prefix (= total) -> fill invalid tail slice
// ---------------------------------------------------------------------------
__global__ void __launch_bounds__(NTHR, 2)
mega_kernel(const float* __restrict__ pos,
            const int*   __restrict__ batch,
            float*       __restrict__ out)
{
    __shared__ unsigned smask[ROWS_PER_BLOCK][MASK_WORDS];   // 32 KB
    __shared__ int scnt[ROWS_PER_BLOCK];
    __shared__ int srowoff[ROWS_PER_BLOCK];
    __shared__ int stotal;

    const int t    = threadIdx.x;
    const int b    = blockIdx.x;
    const int warp = t >> 5;
    const int lane = t & 31;

    // ---- phase 0: zero global scratch + shared masks ----
    if (t < 3) {
        const int k = t * NBLK + b;
        if (k < NCELLS) g_cell_cnt[k] = 0;
    }
    if (t == 0) g_state[b] = 0u;
    #pragma unroll
    for (int k = t; k < ROWS_PER_BLOCK * MASK_WORDS; k += NTHR)
        ((unsigned*)smask)[k] = 0u;
    gbar();

    // ---- phase 1: bucketed cell list (block b owns atoms [32b, 32b+32)) ----
    if (t < 32) {
        const int i = b * 32 + t;
        const float x = pos[3 * i + 0];
        const float y = pos[3 * i + 1];
        const float z = pos[3 * i + 2];
        const int c = cell_coord(x) * 81 + cell_coord(y) * 9 + cell_coord(z);
        const int slot = atomicAdd(&g_cell_cnt[c], 1);
        if (slot < CAP) {
            g_bpos[c * CAP + slot]   = make_float4(x, y, z, __int_as_float(i));
            g_bbatch[c * CAP + slot] = batch[i];
        }
    }
    gbar();

    // ---- phase 2a: masks + counts for this block's 32 rows (2 per warp) ----
    const int rbase = b * ROWS_PER_BLOCK;
    #pragma unroll
    for (int rr = 0; rr < 2; rr++) {
        const int r = warp * 2 + rr;
        const int i = rbase + r;
        const float pix = pos[3 * i + 0];
        const float piy = pos[3 * i + 1];
        const float piz = pos[3 * i + 2];
        build_row_mask(i, pix, piy, piz, batch[i], smask[r], lane);
        __syncwarp();
        int cnt = 0;
        #pragma unroll
        for (int k = 0; k < 8; k++) cnt += __popc(smask[r][lane * 8 + k]);
        cnt = __reduce_add_sync(FULLMASK, cnt);
        if (lane == 0) scnt[r] = cnt;
    }
    __syncthreads();

    // ---- phase 2b: decoupled lookback (warp 0; lane l owns row rbase+l) ----
    if (warp == 0) {
        const int myc = scnt[lane];
        int incl = myc;
        #pragma unroll
        for (int d = 1; d < 32; d <<= 1) {
            const int u = __shfl_up_sync(FULLMASK, incl, d);
            if (lane >= d) incl += u;
        }
        const int agg = __shfl_sync(FULLMASK, incl, 31);
        if (lane == 0) atomicExch(&g_state[b], (1u << 30) | (unsigned)agg);

        int excl = 0;
        int look = b - 1;
        bool done = (look < 0);
        while (!done) {
            const int idx = look - lane;
            unsigned v;
            if (idx >= 0) {
                do { v = *(volatile unsigned*)&g_state[idx]; } while (v == 0u);
            } else {
                v = (2u << 30);               // virtual PREFIX=0 before block 0
            }
            const unsigned flag = v >> 30;
            const int val = (int)(v & 0x3FFFFFFFu);
            const unsigned pmask = __ballot_sync(FULLMASK, flag == 2u);
            const int limit = (pmask != 0u) ? (__ffs(pmask) - 1) : 31;
            int contrib = (lane <= limit) ? val : 0;
            #pragma unroll
            for (int d = 16; d > 0; d >>= 1)
                contrib += __shfl_down_sync(FULLMASK, contrib, d);
            contrib = __shfl_sync(FULLMASK, contrib, 0);
            excl += contrib;
            if (pmask != 0u) done = true; else look -= 32;
        }
        if (lane == 0)
            atomicExch(&g_state[b], (2u << 30) | (unsigned)(excl + agg));
        srowoff[lane] = excl + incl - myc;    // global exclusive row offset
    }
    __syncthreads();

    // ---- phase 2c: ordered writes. lane l owns j in [256l, 256(l+1)) ----
    float* __restrict__ outI = out;
    float* __restrict__ outJ = out + MAX_PAIRS;
    float* __restrict__ outW = out + 2 * MAX_PAIRS;
    float* __restrict__ outV = out + 3 * MAX_PAIRS;

    #pragma unroll
    for (int rr = 0; rr < 2; rr++) {
        const int r = warp * 2 + rr;
        const int i = rbase + r;
        const float pix = pos[3 * i + 0];
        const float piy = pos[3 * i + 1];
        const float piz = pos[3 * i + 2];
        const float fi  = (float)i;

        unsigned w8[8];
        #pragma unroll
        for (int k = 0; k < 8; k++) w8[k] = smask[r][lane * 8 + k];

        int myc = 0;
        #pragma unroll
        for (int k = 0; k < 8; k++) myc += __popc(w8[k]);

        int incl = myc;
        #pragma unroll
        for (int d = 1; d < 32; d <<= 1) {
            const int u = __shfl_up_sync(FULLMASK, incl, d);
            if (lane >= d) incl += u;
        }
        int p = srowoff[r] + incl - myc;

        #pragma unroll
        for (int k = 0; k < 8; k++) {
            unsigned word = w8[k];
            const int jbase = (lane * 8 + k) * 32;
            while (word) {
                const int bpos = __ffs(word) - 1;
                word &= word - 1;
                const int j = jbase + bpos;
                const float dx = pix - pos[3 * j + 0];
                const float dy = piy - pos[3 * j + 1];
                const float dz = piz - pos[3 * j + 2];
                const float d2 = d2_exact(dx, dy, dz);
                if (p < MAX_PAIRS) {
                    outI[p] = fi;
                    outJ[p] = (float)j;
                    outW[p] = sqrtf(d2);
                    outV[3 * p + 0] = dx;
                    outV[3 * p + 1] = dy;
                    outV[3 * p + 2] = dz;
                }
                p++;
            }
        }
    }

    // ---- phase 3: tail fill. total = final inclusive prefix of block 255 ----
    if (t == 0) {
        unsigned v;
        do { v = *(volatile unsigned*)&g_state[NBLK - 1]; } while ((v >> 30) != 2u);
        stotal = (int)(v & 0x3FFFFFFFu);
    }
    __syncthreads();
    int total = stotal;
    if (total > MAX_PAIRS) total = MAX_PAIRS;

    const int sbase = b * SLOTS_PER_BLOCK;
    for (int k = t; k < SLOTS_PER_BLOCK; k += NTHR) {
        const int p = sbase + k;
        if (p >= total) {
            outI[p] = -1.0f;
            outJ[p] = -1.0f;
            outW[p] = 0.0f;
            outV[3 * p + 0] = 0.0f;
            outV[3 * p + 1] = 0.0f;
            outV[3 * p + 2] = 0.0f;
        }
    }
}

// ---------------------------------------------------------------------------
extern "C" void kernel_launch(void* const* d_in, const int* in_sizes, int n_in,
                              void* d_out, int out_size) {
    const float* pos   = (const float*)d_in[0];   // [8192, 3] f32
    const int*   batch = (const int*)d_in[1];     // [8192] i32
    float* out = (float*)d_out;                   // 6 * MAX_PAIRS floats

    (void)in_sizes; (void)n_in; (void)out_size;

    mega_kernel<<<NBLK, NTHR>>>(pos, batch, out);
}

// round 5
// speedup vs baseline: 1.3782x; 1.3782x over previous
#include <cuda_runtime.h>
#include <math.h>

// Problem constants (fixed by the reference)
#define NATOMS     8192
#define MAX_PAIRS  (64 * 8192)     // 524288
#define CUT2       25.0f           // cutoff_upper^2; cutoff_lower = 0
#define NCELL1     9               // 45.0 / 5.0
#define NCELLS     (NCELL1 * NCELL1 * NCELL1)   // 729
#define CAP        48              // bucket capacity (Poisson mean 11.2, max ~30)
#define MASK_WORDS 256             // 8192 bits per row
#define NBLK       1024            // pairs grid: 8 rows (warps) per block
#define FULLMASK   0xffffffffu

// Scratch (device globals; zero-initialized at load; K3 restores the zeros
// after every run so each graph replay starts from the same state)
__device__ int      g_cell_cnt[NCELLS];
__device__ float4   g_bpos[NCELLS * CAP];    // (x, y, z, atom_idx bits)
__device__ int      g_bbatch[NCELLS * CAP];
__device__ unsigned g_state[NBLK];           // decoupled-lookback state
__device__ int      g_total;

// d2 with the SAME rounding as the reference: rounded products, then ((a+b)+c).
__device__ __forceinline__ float d2_exact(float dx, float dy, float dz) {
    float a = __fmul_rn(dx, dx);
    float b = __fmul_rn(dy, dy);
    float c = __fmul_rn(dz, dz);
    return __fadd_rn(__fadd_rn(a, b), c);
}

__device__ __forceinline__ int cell_coord(float p) {
    int c = (int)(p * 0.2f);
    return c < 0 ? 0 : (c > NCELL1 - 1 ? NCELL1 - 1 : c);
}

// ---------------------------------------------------------------------------
// K1: bucketed cell-list build. One thread per atom; g_cell_cnt arrives
// zeroed (load-time init / restored by K3 at the end of the previous run).
// ---------------------------------------------------------------------------
__global__ void build_kernel(const float* __restrict__ pos,
                             const int*   __restrict__ batch) {
    const int i = blockIdx.x * blockDim.x + threadIdx.x;
    if (i >= NATOMS) return;
    const float x = pos[3 * i + 0];
    const float y = pos[3 * i + 1];
    const float z = pos[3 * i + 2];
    const int c = cell_coord(x) * 81 + cell_coord(y) * 9 + cell_coord(z);
    const int slot = atomicAdd(&g_cell_cnt[c], 1);
    if (slot < CAP) {
        g_bpos[c * CAP + slot]   = make_float4(x, y, z, __int_as_float(i));
        g_bbatch[c * CAP + slot] = batch[i];
    }
}

// ---------------------------------------------------------------------------
// K2: fused count + global scan (decoupled lookback) + ordered write.
// One warp per row i, 8 rows per block. Candidates walked per (ix,iy) strip
// with lanes partitioned across the 2-3 z-cells -> ~full lane utilization.
// Row bitmask in shared gives exact row-major (i, ascending-j) order.
// ---------------------------------------------------------------------------
__global__ void pairs_kernel(const float* __restrict__ pos,
                             const int*   __restrict__ batch,
                             float*       __restrict__ out) {
    __shared__ unsigned smask[8][MASK_WORDS];
    __shared__ int scnt[8];
    __shared__ int srowoff[8];
    const int warp = threadIdx.x >> 5;
    const int lane = threadIdx.x & 31;
    const int b = blockIdx.x;
    const int i = b * 8 + warp;

    for (int k = lane; k < MASK_WORDS; k += 32) smask[warp][k] = 0;

    const float pix = pos[3 * i + 0];
    const float piy = pos[3 * i + 1];
    const float piz = pos[3 * i + 2];
    const int   bi  = batch[i];
    __syncwarp();

    const int cx = cell_coord(pix), cy = cell_coord(piy), cz = cell_coord(piz);
    const int x0 = max(cx - 1, 0), x1 = min(cx + 1, NCELL1 - 1);
    const int y0 = max(cy - 1, 0), y1 = min(cy + 1, NCELL1 - 1);
    const int z0 = max(cz - 1, 0), z1 = min(cz + 1, NCELL1 - 1);
    const int nz = z1 - z0;                    // 1 or 2 (extra cells beyond c0)

    for (int ix = x0; ix <= x1; ix++) {
        for (int iy = y0; iy <= y1; iy++) {
            const int c0 = ix * 81 + iy * 9 + z0;
            int n0 = g_cell_cnt[c0];            n0 = n0 > CAP ? CAP : n0;
            int n1 = (nz >= 1) ? g_cell_cnt[c0 + 1] : 0; n1 = n1 > CAP ? CAP : n1;
            int n2 = (nz >= 2) ? g_cell_cnt[c0 + 2] : 0; n2 = n2 > CAP ? CAP : n2;
            const int n01 = n0 + n1;
            const int tot = n01 + n2;
            for (int s = lane; s < tot; s += 32) {
                int cc, off;
                if (s < n0)       { cc = c0;     off = s; }
                else if (s < n01) { cc = c0 + 1; off = s - n0; }
                else              { cc = c0 + 2; off = s - n01; }
                const int slot = cc * CAP + off;
                const float4 pj = g_bpos[slot];
                const float dx = pix - pj.x;
                const float dy = piy - pj.y;
                const float dz = piz - pj.z;
                const float d2 = d2_exact(dx, dy, dz);
                const int j = __float_as_int(pj.w);
                if (d2 < CUT2 && j != i && g_bbatch[slot] == bi) {
                    atomicOr(&smask[warp][j >> 5], 1u << (j & 31));
                }
            }
        }
    }
    __syncwarp();

    // per-row count from the mask
    int cnt = 0;
    #pragma unroll
    for (int k = 0; k < 8; k++) cnt += __popc(smask[warp][lane * 8 + k]);
    cnt = __reduce_add_sync(FULLMASK, cnt);
    if (lane == 0) scnt[warp] = cnt;
    __syncthreads();

    // warp 0: publish aggregate, decoupled lookback, publish inclusive prefix
    if (warp == 0) {
        int agg = 0;
        if (lane == 0) {
            #pragma unroll
            for (int r = 0; r < 8; r++) agg += scnt[r];
            atomicExch(&g_state[b], (1u << 30) | (unsigned)agg);
        }
        agg = __shfl_sync(FULLMASK, agg, 0);

        int excl = 0;
        int look = b - 1;
        bool done = (look < 0);
        while (!done) {
            const int idx = look - lane;
            unsigned v;
            if (idx >= 0) {
                do { v = *(volatile unsigned*)&g_state[idx]; } while (v == 0u);
            } else {
                v = (2u << 30);               // virtual PREFIX=0 before block 0
            }
            const unsigned flag = v >> 30;
            const int val = (int)(v & 0x3FFFFFFFu);
            const unsigned pmask = __ballot_sync(FULLMASK, flag == 2u);
            const int limit = (pmask != 0u) ? (__ffs(pmask) - 1) : 31;
            int contrib = (lane <= limit) ? val : 0;
            #pragma unroll
            for (int d = 16; d > 0; d >>= 1)
                contrib += __shfl_down_sync(FULLMASK, contrib, d);
            contrib = __shfl_sync(FULLMASK, contrib, 0);
            excl += contrib;
            if (pmask != 0u) done = true; else look -= 32;
        }
        if (lane == 0) {
            atomicExch(&g_state[b], (2u << 30) | (unsigned)(excl + agg));
            if (b == NBLK - 1) g_total = excl + agg;
            int run = excl;
            #pragma unroll
            for (int r = 0; r < 8; r++) { srowoff[r] = run; run += scnt[r]; }
        }
    }
    __syncthreads();

    // ordered write: lane l owns words [8l, 8l+8) -> j in [256l, 256(l+1))
    unsigned w8[8];
    #pragma unroll
    for (int t = 0; t < 8; t++) w8[t] = smask[warp][lane * 8 + t];

    int myc = 0;
    #pragma unroll
    for (int t = 0; t < 8; t++) myc += __popc(w8[t]);

    int incl = myc;
    #pragma unroll
    for (int d = 1; d < 32; d <<= 1) {
        int u = __shfl_up_sync(FULLMASK, incl, d);
        if (lane >= d) incl += u;
    }
    int p = srowoff[warp] + incl - myc;

    const float fi = (float)i;
    float* __restrict__ outI = out;
    float* __restrict__ outJ = out + MAX_PAIRS;
    float* __restrict__ outW = out + 2 * MAX_PAIRS;
    float* __restrict__ outV = out + 3 * MAX_PAIRS;

    #pragma unroll
    for (int t = 0; t < 8; t++) {
        unsigned word = w8[t];
        const int jbase = (lane * 8 + t) * 32;
        while (word) {
            const int bpos = __ffs(word) - 1;
            word &= word - 1;
            const int j = jbase + bpos;
            const float dx = pix - pos[3 * j + 0];
            const float dy = piy - pos[3 * j + 1];
            const float dz = piz - pos[3 * j + 2];
            const float d2 = d2_exact(dx, dy, dz);
            if (p < MAX_PAIRS) {
                outI[p] = fi;
                outJ[p] = (float)j;
                outW[p] = sqrtf(d2);
                outV[3 * p + 0] = dx;
                outV[3 * p + 1] = dy;
                outV[3 * p + 2] = dz;
            }
            p++;
        }
    }
}

// ---------------------------------------------------------------------------
// K3: fill the INVALID tail [total, MAX_PAIRS) with defaults, and restore
// scratch (g_cell_cnt, g_state) to zero so the next replay starts clean.
// ---------------------------------------------------------------------------
__global__ void filltail_kernel(float* __restrict__ out) {
    const long long MP = MAX_PAIRS;
    const long long e = (long long)blockIdx.x * blockDim.x + threadIdx.x;

    // restore scratch zeros (first few blocks; disjoint from any reader)
    if (blockIdx.x == 0 && threadIdx.x < NCELLS) {
        if (threadIdx.x == 0) { /* nothing */ }
        g_cell_cnt[threadIdx.x] = 0;
    }
    if (blockIdx.x == 1) {
        for (int k = threadIdx.x; k < NBLK; k += blockDim.x) g_state[k] = 0u;
    }

    if (e >= 6 * MP) return;
    int total = g_total;
    if (total > MAX_PAIRS) total = MAX_PAIRS;

    if (e < 2 * MP) {                                   // edge_index (i then j)
        if ((int)(e >= MP ? e - MP : e) >= total) out[e] = -1.0f;
    } else if (e < 3 * MP) {                            // edge_weight
        if ((int)(e - 2 * MP) >= total) out[e] = 0.0f;
    } else {                                            // edge_vec [MP,3]
        if ((e - 3 * MP) >= 3LL * total) out[e] = 0.0f;
    }
}

// ---------------------------------------------------------------------------
extern "C" void kernel_launch(void* const* d_in, const int* in_sizes, int n_in,
                              void* d_out, int out_size) {
    const float* pos   = (const float*)d_in[0];   // [8192, 3] f32
    const int*   batch = (const int*)d_in[1];     // [8192] i32
    float* out = (float*)d_out;                   // 6 * MAX_PAIRS floats

    (void)in_sizes; (void)n_in; (void)out_size;

    build_kernel<<<NATOMS / 256, 256>>>(pos, batch);
    pairs_kernel<<<NBLK, 256>>>(pos, batch, out);
    const long long total = 6LL * MAX_PAIRS;
    filltail_kernel<<<(int)((total + 1023) / 1024), 1024>>>(out);
}